// round 1
// baseline (speedup 1.0000x reference)
#include <cuda_runtime.h>

#define Hd   512
#define BB   128
#define SEQL 512

// Scratch (device globals — no allocation allowed).
// g_TP: 15 matrix "power" slots, 512x512 each:
//   slot 0..7  = AT^1..AT^8   (AT = A transposed, row-major)
//   slot 8..14 = AT^16,24,32,40,48,56,64
__device__ float g_TP[15 * Hd * Hd];
// y-scan ping-pong: 2 x [8 groups][128 batch][512]
__device__ float g_Y[2 * 8 * BB * Hd];
// s_c chunk-start states: [64 chunks][128 batch][512]
__device__ float g_S[64 * BB * Hd];

// ---------------------------------------------------------------------------
// AT = A^T
__global__ void transpose_kernel(float* __restrict__ dst, const float* __restrict__ src) {
    __shared__ float tile[32][33];
    int bx = blockIdx.x * 32, by = blockIdx.y * 32;
#pragma unroll
    for (int i = 0; i < 32; i += 8)
        tile[threadIdx.y + i][threadIdx.x] = src[(by + threadIdx.y + i) * Hd + bx + threadIdx.x];
    __syncthreads();
#pragma unroll
    for (int i = 0; i < 32; i += 8)
        dst[(bx + threadIdx.y + i) * Hd + by + threadIdx.x] = tile[threadIdx.x][threadIdx.y + i];
}

__global__ void zero_kernel(float* p, int n) {
    int i = (blockIdx.x * blockDim.x + threadIdx.x) * 4;
    if (i < n) *reinterpret_cast<float4*>(p + i) = make_float4(0.f, 0.f, 0.f, 0.f);
}

// copy M rows of 512 floats; row offset = (m>>7)*gs + (m&127)*bs
__global__ void copy_rows_kernel(float* __restrict__ dst, int gsD, int bsD,
                                 const float* __restrict__ src, int gsS, int bsS) {
    int m = blockIdx.x;
    size_t so = (size_t)(m >> 7) * gsS + (size_t)(m & 127) * bsS;
    size_t dofs = (size_t)(m >> 7) * gsD + (size_t)(m & 127) * bsD;
    reinterpret_cast<float4*>(dst + dofs)[threadIdx.x] =
        reinterpret_cast<const float4*>(src + so)[threadIdx.x];
}

// ---------------------------------------------------------------------------
// Unified fp32 GEMM: C[m,:] (+)= sum_k Arow(m)[k] * B[k,:]  (+ optional W row)
// All row addressing via: off(m) = (m>>7)*gs + (m&127)*bs   (+ z*zs for B/C)
// K = N = 512 fixed.
template <int BM, int BN, int TM, int TN, bool ACCUM, bool ADDW>
__global__ __launch_bounds__(256) void gemm_kernel(
    const float* __restrict__ A, int gsA, int bsA,
    const float* __restrict__ Bm, int zsB,
    float* __restrict__ C, int gsC, int bsC, int zsC,
    const float* __restrict__ W, int gsW, int bsW)
{
    constexpr int KT = 16;
    __shared__ float As[KT][BM];
    __shared__ float Bs[KT][BN];

    const int tid = threadIdx.x;
    const int m0 = blockIdx.y * BM;
    const int n0 = blockIdx.x * BN;
    const int z  = blockIdx.z;
    const float* Bz = Bm + (size_t)z * zsB;

    constexpr int NTX = BN / TN;
    const int tx = tid % NTX;
    const int ty = tid / NTX;
    const int tm = ty * TM;
    const int tn = tx * TN;

    float acc[TM][TN] = {};

    constexpr int ALD = BM * 4 / 256;  // float4 loads per thread per k-tile
    constexpr int BLD = BN * 4 / 256;

    for (int k0 = 0; k0 < Hd; k0 += KT) {
#pragma unroll
        for (int l = 0; l < ALD; l++) {
            int i = tid + l * 256;          // [0, BM*4)
            int row = i >> 2;
            int c4  = (i & 3) << 2;
            int m = m0 + row;
            float4 v = *reinterpret_cast<const float4*>(
                A + (size_t)(m >> 7) * gsA + (size_t)(m & 127) * bsA + k0 + c4);
            As[c4 + 0][row] = v.x;
            As[c4 + 1][row] = v.y;
            As[c4 + 2][row] = v.z;
            As[c4 + 3][row] = v.w;
        }
#pragma unroll
        for (int l = 0; l < BLD; l++) {
            int i = tid + l * 256;          // [0, BN*4)
            int r  = i / (BN / 4);
            int c4 = (i % (BN / 4)) << 2;
            *reinterpret_cast<float4*>(&Bs[r][c4]) =
                *reinterpret_cast<const float4*>(Bz + (size_t)(k0 + r) * Hd + n0 + c4);
        }
        __syncthreads();
#pragma unroll
        for (int kk = 0; kk < KT; kk++) {
            float a[TM], b[TN];
#pragma unroll
            for (int i = 0; i < TM; i += 4)
                *reinterpret_cast<float4*>(&a[i]) =
                    *reinterpret_cast<const float4*>(&As[kk][tm + i]);
#pragma unroll
            for (int j = 0; j < TN; j += 4)
                *reinterpret_cast<float4*>(&b[j]) =
                    *reinterpret_cast<const float4*>(&Bs[kk][tn + j]);
#pragma unroll
            for (int i = 0; i < TM; i++)
#pragma unroll
                for (int j = 0; j < TN; j++)
                    acc[i][j] = fmaf(a[i], b[j], acc[i][j]);
        }
        __syncthreads();
    }

#pragma unroll
    for (int i = 0; i < TM; i++) {
        int m = m0 + tm + i;
        size_t coff = (size_t)(m >> 7) * gsC + (size_t)(m & 127) * bsC +
                      (size_t)z * zsC + n0 + tn;
        size_t woff = 0;
        if (ADDW) woff = (size_t)(m >> 7) * gsW + (size_t)(m & 127) * bsW + n0 + tn;
#pragma unroll
        for (int j = 0; j < TN; j += 4) {
            float4 v = make_float4(acc[i][j], acc[i][j + 1], acc[i][j + 2], acc[i][j + 3]);
            if (ACCUM) {
                float4 c = *reinterpret_cast<const float4*>(C + coff + j);
                v.x += c.x; v.y += c.y; v.z += c.z; v.w += c.w;
            }
            if (ADDW) {
                float4 w = *reinterpret_cast<const float4*>(W + woff + j);
                v.x += w.x; v.y += w.y; v.z += w.z; v.w += w.w;
            }
            *reinterpret_cast<float4*>(C + coff + j) = v;
        }
    }
}

#define G64   gemm_kernel<64, 64, 4, 4, false, false>
#define G64W  gemm_kernel<64, 64, 4, 4, false, true>
#define G64A  gemm_kernel<64, 64, 4, 4, true,  false>
#define G128  gemm_kernel<128, 128, 8, 8, false, false>
#define G128A gemm_kernel<128, 128, 8, 8, true,  false>

// ---------------------------------------------------------------------------
// Algorithm (row-vector convention, h_t = h_{t-1} @ AT + u_t):
//  1. U = X @ B               -> d_out          (u'_t)
//  2. u'_0 += h0 @ AT                          (fold initial state)
//  3. 64 chunks of 8: local scans from zero (7 batched sequential steps,
//     in place in d_out):  d_out[t] += d_out[t-1] @ AT       => v_{c,k}
//  4. chunk totals w_c = v_{c,7} (rows t = 8c+7 of d_out)
//     y-scan over 8 groups of 8 chunks -> group totals W_g
//     group scan (AT^64) -> group starts; within-group scan (AT^8) -> all s_c
//  5. corrections: d_out[8c+k] += s_c @ AT^{k+1}   (8 batched GEMMs, one launch)
// ---------------------------------------------------------------------------
extern "C" void kernel_launch(void* const* d_in, const int* in_sizes, int n_in,
                              void* d_out, int out_size) {
    const float* h0 = (const float*)d_in[0];
    const float* x  = (const float*)d_in[1];
    const float* Am = (const float*)d_in[2];
    const float* Bm = (const float*)d_in[3];
    float* out = (float*)d_out;

    float *TP, *Y, *S;
    cudaGetSymbolAddress((void**)&TP, g_TP);
    cudaGetSymbolAddress((void**)&Y, g_Y);
    cudaGetSymbolAddress((void**)&S, g_S);

    const int MM   = Hd * Hd;    // 262144, one 512x512 matrix
    const int BROW = SEQL * Hd;  // 262144, batch stride in out

    // 1. AT = A^T  -> slot 0
    transpose_kernel<<<dim3(16, 16), dim3(32, 8)>>>(TP, Am);

    // 2. powers of AT (batched; A operand fixed per level, B/C slide by z*MM)
    //    s1=AT^2 | s2=AT^3,s3=AT^4 | s4..7=AT^5..8 | s8=AT^16 | s9,s10=AT^24,32 | s11..14=AT^40..64
    G64<<<dim3(8, 8, 1), 256>>>(TP + 0*MM, 65536, 512, TP + 0*MM, 0,  TP + 1*MM, 65536, 512, 0,  nullptr, 0, 0);
    G64<<<dim3(8, 8, 2), 256>>>(TP + 1*MM, 65536, 512, TP + 0*MM, MM, TP + 2*MM, 65536, 512, MM, nullptr, 0, 0);
    G64<<<dim3(8, 8, 4), 256>>>(TP + 3*MM, 65536, 512, TP + 0*MM, MM, TP + 4*MM, 65536, 512, MM, nullptr, 0, 0);
    G64<<<dim3(8, 8, 1), 256>>>(TP + 7*MM, 65536, 512, TP + 7*MM, 0,  TP + 8*MM, 65536, 512, 0,  nullptr, 0, 0);
    G64<<<dim3(8, 8, 2), 256>>>(TP + 8*MM, 65536, 512, TP + 7*MM, MM, TP + 9*MM, 65536, 512, MM, nullptr, 0, 0);
    G64<<<dim3(8, 8, 4), 256>>>(TP + 10*MM, 65536, 512, TP + 7*MM, MM, TP + 11*MM, 65536, 512, MM, nullptr, 0, 0);

    // 3. U = X @ B  (M = 65536)
    G128<<<dim3(4, 512), 256>>>(x, 65536, 512, Bm, 0, out, 65536, 512, 0, nullptr, 0, 0);

    // 4. fold h0 into t=0 rows: out[b,0,:] += h0[b,:] @ AT
    G64A<<<dim3(8, 2), 256>>>(h0, 0, 512, TP, 0, out, 0, BROW, 0, nullptr, 0, 0);

    // 5. local scans, k = 1..7: rows t=8c+k += rows t=8c+k-1 @ AT  (M = 8192)
    for (int k = 1; k < 8; k++)
        G128A<<<dim3(4, 64), 256>>>(out + (size_t)(k - 1) * Hd, 4096, BROW, TP, 0,
                                    out + (size_t)k * Hd, 4096, BROW, 0, nullptr, 0, 0);

    // 6. y-scan (8 groups of 8 chunks): y_{g,1} = w_{8g}; y_{g,j} = y_{g,j-1}@AT^8 + w_{8g+j-1}
    copy_rows_kernel<<<1024, 128>>>(Y, 65536, 512, out + 7 * Hd, 32768, BROW);
    int cur = 0;
    for (int j = 2; j <= 8; j++) {
        G64W<<<dim3(8, 16), 256>>>(Y + (size_t)cur * 524288, 65536, 512, TP + 7*MM, 0,
                                   Y + (size_t)(1 - cur) * 524288, 65536, 512, 0,
                                   out + (size_t)(8 * j - 1) * Hd, 32768, BROW);
        cur ^= 1;
    }
    const float* Wg = Y + 524288;  // cur ends at 1: group totals live in buffer 1

    // 7. group-start scan: S[0]=0; S[8g] = S[8(g-1)] @ AT^64 + W_{g-1}
    zero_kernel<<<64, 256>>>(S, 65536);
    for (int g = 1; g < 8; g++)
        G64W<<<dim3(8, 2), 256>>>(S + (size_t)(g - 1) * 8 * 65536, 0, 512, TP + 14*MM, 0,
                                  S + (size_t)g * 8 * 65536, 0, 512, 0,
                                  Wg + (size_t)(g - 1) * 65536, 0, 512);

    // 8. within-group scan, j=1..7 (batched over g):
    //    s_{8g+j} = s_{8g+j-1} @ AT^8 + w_{8g+j-1}
    for (int j = 1; j < 8; j++)
        G64W<<<dim3(8, 16), 256>>>(S + (size_t)(j - 1) * 65536, 524288, 512, TP + 7*MM, 0,
                                   S + (size_t)j * 65536, 524288, 512, 0,
                                   out + (size_t)(8 * j - 1) * Hd, 32768, BROW);

    // 9. corrections (z = k = 0..7): out[b, 8c+k, :] += s_c @ AT^{k+1}
    G128A<<<dim3(4, 64, 8), 256>>>(S, 65536, 512, TP, MM,
                                   out, 4096, BROW, Hd, nullptr, 0, 0);
}

// round 3
// speedup vs baseline: 1.8179x; 1.8179x over previous
#include <cuda_runtime.h>
#include <cuda_bf16.h>
#include <cstdint>

#define Hd   512
#define BB   128
#define SEQL 512

// ---------------------------------------------------------------------------
// Device scratch (no allocation allowed)
// g_TP: fp32 AT powers: slot0..7 = AT^1..AT^8, slot8..14 = AT^16..AT^64(step 8)
__device__ float g_TP[15 * Hd * Hd];
__device__ float g_Y[2 * 8 * BB * Hd];
__device__ float g_S[64 * BB * Hd];
// bf16 split B-operands ([N,K] K-major): slot0 = Bm^T, slot p(1..8) = A^p
__device__ __nv_bfloat16 g_BH[9 * Hd * Hd];
__device__ __nv_bfloat16 g_BL[9 * Hd * Hd];

__device__ __forceinline__ uint32_t smem_u32(const void* p) {
    uint32_t a;
    asm("{ .reg .u64 t; cvta.to.shared.u64 t, %1; cvt.u32.u64 %0, t; }" : "=r"(a) : "l"(p));
    return a;
}

__device__ __forceinline__ uint32_t pack_bf2(float a, float b) {
    __nv_bfloat162 t;
    t.x = __float2bfloat16(a);
    t.y = __float2bfloat16(b);
    return *reinterpret_cast<uint32_t*>(&t);
}

__device__ __forceinline__ void ldm_x4(uint32_t* r, uint32_t addr) {
    asm volatile("ldmatrix.sync.aligned.m8n8.x4.shared.b16 {%0,%1,%2,%3}, [%4];"
                 : "=r"(r[0]), "=r"(r[1]), "=r"(r[2]), "=r"(r[3]) : "r"(addr));
}

__device__ __forceinline__ void mma16816(float* d, const uint32_t* a, const uint32_t* b) {
    asm volatile(
        "mma.sync.aligned.m16n8k16.row.col.f32.bf16.bf16.f32 "
        "{%0,%1,%2,%3}, {%4,%5,%6,%7}, {%8,%9}, {%0,%1,%2,%3};"
        : "+f"(d[0]), "+f"(d[1]), "+f"(d[2]), "+f"(d[3])
        : "r"(a[0]), "r"(a[1]), "r"(a[2]), "r"(a[3]), "r"(b[0]), "r"(b[1]));
}

// ---------------------------------------------------------------------------
// HMMA bf16-split GEMM: C[m, n0..n0+127] (+)= sum_k Afp32[m,k] * Bop^T[k,n]
// Bop pre-split bf16 hi/lo, [N=512, K=512] row-major (K-major).
// Row addressing: off(m) = (m>>7)*gs + (m&127)*bs ; B adds z*zsB; C adds z*zsC.
// Tiles: BM=128, BN=128, BK=32 (16 chunks), double buffered.
// SMEM per stage: Ah(128x40 bf16) | Al | Bh | Bl  = 4 x 10240 B = 40960 B.
#define STAGE_B 40960
#define SMEM_HM (2 * STAGE_B)

template <bool ACCUM>
__global__ __launch_bounds__(256, 2) void hmma_gemm(
    const float* __restrict__ A, int gsA, int bsA,
    const __nv_bfloat16* __restrict__ Bh, const __nv_bfloat16* __restrict__ Bl, int zsB,
    float* __restrict__ C, int gsC, int bsC, int zsC)
{
    extern __shared__ char smem_raw[];
    const uint32_t sbase = smem_u32(smem_raw);

    const int tid = threadIdx.x;
    const int lane = tid & 31;
    const int wm = (tid >> 5) & 3;          // warp M index (4)
    const int wn = tid >> 7;                // warp N index (2)
    const int m0 = blockIdx.y * 128;
    const int n0 = blockIdx.x * 128;
    const int z  = blockIdx.z;
    const __nv_bfloat16* Bhz = Bh + (size_t)z * zsB;
    const __nv_bfloat16* Blz = Bl + (size_t)z * zsB;

    float acc[2][8][4] = {};
    float4 areg[4];

    // B: cp.async gmem(bf16) -> smem, 16B each; 512 chunks per matrix
    auto cpB = [&](int kc, int s) {
        int k0 = kc * 32;
#pragma unroll
        for (int l = 0; l < 2; l++) {
            int i = tid + l * 256;
            int r = i >> 2, c = i & 3;
            uint32_t so = sbase + s * STAGE_B + 20480 + r * 80 + c * 16;
            const void* gh = Bhz + (size_t)(n0 + r) * Hd + k0 + c * 8;
            const void* gl = Blz + (size_t)(n0 + r) * Hd + k0 + c * 8;
            asm volatile("cp.async.cg.shared.global [%0], [%1], 16;" :: "r"(so), "l"(gh));
            asm volatile("cp.async.cg.shared.global [%0], [%1], 16;" :: "r"(so + 10240), "l"(gl));
        }
    };
    // A: fp32 gmem -> regs (prefetch)
    auto ldA = [&](int kc) {
        int k0 = kc * 32;
#pragma unroll
        for (int l = 0; l < 4; l++) {
            int i = tid + l * 256;
            int r = i >> 3, c4 = i & 7;
            int m = m0 + r;
            areg[l] = *reinterpret_cast<const float4*>(
                A + (size_t)(m >> 7) * gsA + (size_t)(m & 127) * bsA + k0 + c4 * 4);
        }
    };
    // A: regs -> split bf16 hi/lo -> smem
    auto stA = [&](int s) {
#pragma unroll
        for (int l = 0; l < 4; l++) {
            int i = tid + l * 256;
            int r = i >> 3, c4 = i & 7;
            float4 v = areg[l];
            __nv_bfloat16 hx = __float2bfloat16(v.x), hy = __float2bfloat16(v.y);
            __nv_bfloat16 hz = __float2bfloat16(v.z), hw = __float2bfloat16(v.w);
            uint32_t h0 = pack_bf2(v.x, v.y), h1 = pack_bf2(v.z, v.w);
            uint32_t l0 = pack_bf2(v.x - __bfloat162float(hx), v.y - __bfloat162float(hy));
            uint32_t l1 = pack_bf2(v.z - __bfloat162float(hz), v.w - __bfloat162float(hw));
            uint32_t so = sbase + s * STAGE_B + r * 80 + c4 * 8;
            asm volatile("st.shared.v2.b32 [%0], {%1,%2};" :: "r"(so), "r"(h0), "r"(h1) : "memory");
            asm volatile("st.shared.v2.b32 [%0], {%1,%2};" :: "r"(so + 10240), "r"(l0), "r"(l1) : "memory");
        }
    };

    // prologue
    cpB(0, 0);
    asm volatile("cp.async.commit_group;" ::: "memory");
    ldA(0);
    stA(0);
    asm volatile("cp.async.wait_group 0;" ::: "memory");
    __syncthreads();

    for (int c = 0; c < 16; c++) {
        int s = c & 1, ns = s ^ 1;
        if (c + 1 < 16) {
            cpB(c + 1, ns);
            asm volatile("cp.async.commit_group;" ::: "memory");
            ldA(c + 1);
        }
        const uint32_t aB = sbase + s * STAGE_B;
        const uint32_t bB = aB + 20480;
#pragma unroll
        for (int ks = 0; ks < 2; ks++) {
            uint32_t ah[2][4], al[2][4];
#pragma unroll
            for (int mt = 0; mt < 2; mt++) {
                int row = wm * 32 + mt * 16 + (lane & 7) + ((lane >> 3) & 1) * 8;
                uint32_t addr = aB + row * 80 + ks * 32 + ((lane >> 4) & 1) * 16;
                ldm_x4(ah[mt], addr);
                ldm_x4(al[mt], addr + 10240);
            }
#pragma unroll
            for (int bt = 0; bt < 4; bt++) {
                uint32_t bh[4], bl[4];
                int nrow = wn * 64 + bt * 16 + (lane & 7) + ((lane >> 4) & 1) * 8;
                uint32_t addr = bB + nrow * 80 + ks * 32 + ((lane >> 3) & 1) * 16;
                ldm_x4(bh, addr);
                ldm_x4(bl, addr + 10240);
#pragma unroll
                for (int mt = 0; mt < 2; mt++) {
#pragma unroll
                    for (int sub = 0; sub < 2; sub++) {
                        int nt = bt * 2 + sub;
                        mma16816(acc[mt][nt], ah[mt], &bh[sub * 2]);
                        mma16816(acc[mt][nt], ah[mt], &bl[sub * 2]);
                        mma16816(acc[mt][nt], al[mt], &bh[sub * 2]);
                    }
                }
            }
        }
        if (c + 1 < 16) {
            stA(ns);
            asm volatile("cp.async.wait_group 0;" ::: "memory");
            __syncthreads();
        }
    }

    // epilogue: c0,c1 -> row grp, cols tig*2+{0,1}; c2,c3 -> row grp+8
    const int grp = lane >> 2, tig = lane & 3;
#pragma unroll
    for (int mt = 0; mt < 2; mt++) {
#pragma unroll
        for (int half = 0; half < 2; half++) {
            int m = m0 + wm * 32 + mt * 16 + grp + half * 8;
            size_t co = (size_t)(m >> 7) * gsC + (size_t)(m & 127) * bsC +
                        (size_t)z * zsC + n0 + wn * 64 + tig * 2;
#pragma unroll
            for (int nt = 0; nt < 8; nt++) {
                float2 v = make_float2(acc[mt][nt][half * 2], acc[mt][nt][half * 2 + 1]);
                float* p = C + co + nt * 8;
                if (ACCUM) {
                    float2 o = *reinterpret_cast<const float2*>(p);
                    v.x += o.x; v.y += o.y;
                }
                *reinterpret_cast<float2*>(p) = v;
            }
        }
    }
}

// ---------------------------------------------------------------------------
// small helper kernels
__global__ void transpose_kernel(float* __restrict__ dst, const float* __restrict__ src) {
    __shared__ float tile[32][33];
    int bx = blockIdx.x * 32, by = blockIdx.y * 32;
#pragma unroll
    for (int i = 0; i < 32; i += 8)
        tile[threadIdx.y + i][threadIdx.x] = src[(by + threadIdx.y + i) * Hd + bx + threadIdx.x];
    __syncthreads();
#pragma unroll
    for (int i = 0; i < 32; i += 8)
        dst[(bx + threadIdx.y + i) * Hd + by + threadIdx.x] = tile[threadIdx.x][threadIdx.y + i];
}

__global__ void zero_kernel(float* p, int n) {
    int i = (blockIdx.x * blockDim.x + threadIdx.x) * 4;
    if (i < n) *reinterpret_cast<float4*>(p + i) = make_float4(0.f, 0.f, 0.f, 0.f);
}

__global__ void copy_rows_kernel(float* __restrict__ dst, int gsD, int bsD,
                                 const float* __restrict__ src, int gsS, int bsS) {
    int m = blockIdx.x;
    size_t so = (size_t)(m >> 7) * gsS + (size_t)(m & 127) * bsS;
    size_t dofs = (size_t)(m >> 7) * gsD + (size_t)(m & 127) * bsD;
    reinterpret_cast<float4*>(dst + dofs)[threadIdx.x] =
        reinterpret_cast<const float4*>(src + so)[threadIdx.x];
}

// split (no transpose): dst[n,k] = src[n,k] as bf16 hi/lo
__global__ void split_kernel(__nv_bfloat16* __restrict__ hi, __nv_bfloat16* __restrict__ lo,
                             const float* __restrict__ src) {
    int i = blockIdx.x * blockDim.x + threadIdx.x;   // float4 index
    float4 v = reinterpret_cast<const float4*>(src)[i];
    uint2 h, l;
    __nv_bfloat16 hx = __float2bfloat16(v.x), hy = __float2bfloat16(v.y);
    __nv_bfloat16 hz = __float2bfloat16(v.z), hw = __float2bfloat16(v.w);
    h.x = pack_bf2(v.x, v.y); h.y = pack_bf2(v.z, v.w);
    l.x = pack_bf2(v.x - __bfloat162float(hx), v.y - __bfloat162float(hy));
    l.y = pack_bf2(v.z - __bfloat162float(hz), v.w - __bfloat162float(hw));
    reinterpret_cast<uint2*>(hi)[i] = h;
    reinterpret_cast<uint2*>(lo)[i] = l;
}

// split-transpose: dst[n,k] = src[k,n] as bf16 hi/lo
__global__ void splitT_kernel(__nv_bfloat16* __restrict__ hi, __nv_bfloat16* __restrict__ lo,
                              const float* __restrict__ src) {
    __shared__ float t[32][33];
    int bx = blockIdx.x * 32, by = blockIdx.y * 32;
#pragma unroll
    for (int i = 0; i < 32; i += 8)
        t[threadIdx.y + i][threadIdx.x] = src[(by + threadIdx.y + i) * Hd + bx + threadIdx.x];
    __syncthreads();
#pragma unroll
    for (int i = 0; i < 32; i += 8) {
        float v = t[threadIdx.x][threadIdx.y + i];
        int n = bx + threadIdx.y + i, k = by + threadIdx.x;
        __nv_bfloat16 h = __float2bfloat16(v);
        hi[n * Hd + k] = h;
        lo[n * Hd + k] = __float2bfloat16(v - __bfloat162float(h));
    }
}

// ---------------------------------------------------------------------------
// SIMT fp32 GEMM for small latency-bound steps (64x64 tiles)
template <int BM, int BN, int TM, int TN, bool ACCUM, bool ADDW>
__global__ __launch_bounds__(256) void gemm_kernel(
    const float* __restrict__ A, int gsA, int bsA,
    const float* __restrict__ Bm, int zsB,
    float* __restrict__ C, int gsC, int bsC, int zsC,
    const float* __restrict__ W, int gsW, int bsW)
{
    constexpr int KT = 16;
    __shared__ float As[KT][BM];
    __shared__ float Bs[KT][BN];
    const int tid = threadIdx.x;
    const int m0 = blockIdx.y * BM;
    const int n0 = blockIdx.x * BN;
    const int z  = blockIdx.z;
    const float* Bz = Bm + (size_t)z * zsB;
    constexpr int NTX = BN / TN;
    const int tx = tid % NTX, ty = tid / NTX;
    const int tm = ty * TM, tn = tx * TN;
    float acc[TM][TN] = {};
    constexpr int ALD = BM * 4 / 256;
    constexpr int BLD = BN * 4 / 256;
    for (int k0 = 0; k0 < Hd; k0 += KT) {
#pragma unroll
        for (int l = 0; l < ALD; l++) {
            int i = tid + l * 256;
            int row = i >> 2, c4 = (i & 3) << 2;
            int m = m0 + row;
            float4 v = *reinterpret_cast<const float4*>(
                A + (size_t)(m >> 7) * gsA + (size_t)(m & 127) * bsA + k0 + c4);
            As[c4 + 0][row] = v.x; As[c4 + 1][row] = v.y;
            As[c4 + 2][row] = v.z; As[c4 + 3][row] = v.w;
        }
#pragma unroll
        for (int l = 0; l < BLD; l++) {
            int i = tid + l * 256;
            int r = i / (BN / 4), c4 = (i % (BN / 4)) << 2;
            *reinterpret_cast<float4*>(&Bs[r][c4]) =
                *reinterpret_cast<const float4*>(Bz + (size_t)(k0 + r) * Hd + n0 + c4);
        }
        __syncthreads();
#pragma unroll
        for (int kk = 0; kk < KT; kk++) {
            float a[TM], b[TN];
#pragma unroll
            for (int i = 0; i < TM; i += 4)
                *reinterpret_cast<float4*>(&a[i]) = *reinterpret_cast<const float4*>(&As[kk][tm + i]);
#pragma unroll
            for (int j = 0; j < TN; j += 4)
                *reinterpret_cast<float4*>(&b[j]) = *reinterpret_cast<const float4*>(&Bs[kk][tn + j]);
#pragma unroll
            for (int i = 0; i < TM; i++)
#pragma unroll
                for (int j = 0; j < TN; j++)
                    acc[i][j] = fmaf(a[i], b[j], acc[i][j]);
        }
        __syncthreads();
    }
#pragma unroll
    for (int i = 0; i < TM; i++) {
        int m = m0 + tm + i;
        size_t coff = (size_t)(m >> 7) * gsC + (size_t)(m & 127) * bsC + (size_t)z * zsC + n0 + tn;
        size_t woff = 0;
        if (ADDW) woff = (size_t)(m >> 7) * gsW + (size_t)(m & 127) * bsW + n0 + tn;
#pragma unroll
        for (int j = 0; j < TN; j += 4) {
            float4 v = make_float4(acc[i][j], acc[i][j + 1], acc[i][j + 2], acc[i][j + 3]);
            if (ACCUM) {
                float4 c = *reinterpret_cast<const float4*>(C + coff + j);
                v.x += c.x; v.y += c.y; v.z += c.z; v.w += c.w;
            }
            if (ADDW) {
                float4 w = *reinterpret_cast<const float4*>(W + woff + j);
                v.x += w.x; v.y += w.y; v.z += w.z; v.w += w.w;
            }
            *reinterpret_cast<float4*>(C + coff + j) = v;
        }
    }
}

#define G64   gemm_kernel<64, 64, 4, 4, false, false>
#define G64W  gemm_kernel<64, 64, 4, 4, false, true>
#define G64A  gemm_kernel<64, 64, 4, 4, true,  false>

// ---------------------------------------------------------------------------
extern "C" void kernel_launch(void* const* d_in, const int* in_sizes, int n_in,
                              void* d_out, int out_size) {
    const float* h0 = (const float*)d_in[0];
    const float* x  = (const float*)d_in[1];
    const float* Am = (const float*)d_in[2];
    const float* Bm = (const float*)d_in[3];
    float* out = (float*)d_out;

    float *TP, *Y, *S;
    __nv_bfloat16 *BSH, *BSL;
    cudaGetSymbolAddress((void**)&TP, g_TP);
    cudaGetSymbolAddress((void**)&Y, g_Y);
    cudaGetSymbolAddress((void**)&S, g_S);
    cudaGetSymbolAddress((void**)&BSH, g_BH);
    cudaGetSymbolAddress((void**)&BSL, g_BL);

    static bool attr_done = false;
    if (!attr_done) {
        cudaFuncSetAttribute(hmma_gemm<false>, cudaFuncAttributeMaxDynamicSharedMemorySize, SMEM_HM);
        cudaFuncSetAttribute(hmma_gemm<true>,  cudaFuncAttributeMaxDynamicSharedMemorySize, SMEM_HM);
        attr_done = true;
    }

    const int MM   = Hd * Hd;     // 262144
    const int BROW = SEQL * Hd;   // 262144

    // 1. AT = A^T -> TP slot 0
    transpose_kernel<<<dim3(16, 16), dim3(32, 8)>>>(TP, Am);

    // 2. AT powers (fp32 SIMT): slots 1..7 = AT^2..AT^8; 8..14 = AT^16..AT^64
    G64<<<dim3(8, 8, 1), 256>>>(TP + 0*MM, 65536, 512, TP + 0*MM, 0,  TP + 1*MM, 65536, 512, 0,  nullptr, 0, 0);
    G64<<<dim3(8, 8, 2), 256>>>(TP + 1*MM, 65536, 512, TP + 0*MM, MM, TP + 2*MM, 65536, 512, MM, nullptr, 0, 0);
    G64<<<dim3(8, 8, 4), 256>>>(TP + 3*MM, 65536, 512, TP + 0*MM, MM, TP + 4*MM, 65536, 512, MM, nullptr, 0, 0);
    G64<<<dim3(8, 8, 1), 256>>>(TP + 7*MM, 65536, 512, TP + 7*MM, 0,  TP + 8*MM, 65536, 512, 0,  nullptr, 0, 0);
    G64<<<dim3(8, 8, 2), 256>>>(TP + 8*MM, 65536, 512, TP + 7*MM, MM, TP + 9*MM, 65536, 512, MM, nullptr, 0, 0);
    G64<<<dim3(8, 8, 4), 256>>>(TP + 10*MM, 65536, 512, TP + 7*MM, MM, TP + 11*MM, 65536, 512, MM, nullptr, 0, 0);

    // 3. bf16 split B-operands: slot0 = Bm^T, slot1 = A, slot p = A^p = (AT^p)^T
    splitT_kernel<<<dim3(16, 16), dim3(32, 8)>>>(BSH + 0*MM, BSL + 0*MM, Bm);
    split_kernel<<<256, 256>>>(BSH + 1*MM, BSL + 1*MM, Am);
    for (int p = 2; p <= 8; p++)
        splitT_kernel<<<dim3(16, 16), dim3(32, 8)>>>(BSH + p*MM, BSL + p*MM, TP + (p - 1)*MM);

    // 4. U = X @ B  (HMMA): M=65536
    hmma_gemm<false><<<dim3(4, 512), 256, SMEM_HM>>>(
        x, 65536, 512, BSH + 0*MM, BSL + 0*MM, 0, out, 65536, 512, 0);

    // 5. fold h0: out[b,0,:] += h0 @ AT  (SIMT)
    G64A<<<dim3(8, 2), 256>>>(h0, 0, 512, TP, 0, out, 0, BROW, 0, nullptr, 0, 0);

    // 6. local scans k=1..7 (HMMA): rows 8c+k += rows 8c+k-1 @ AT
    for (int k = 1; k < 8; k++)
        hmma_gemm<true><<<dim3(4, 64), 256, SMEM_HM>>>(
            out + (size_t)(k - 1) * Hd, 4096, BROW, BSH + 1*MM, BSL + 1*MM, 0,
            out + (size_t)k * Hd, 4096, BROW, 0);

    // 7. y-scan (8 groups of 8 chunk totals)
    copy_rows_kernel<<<1024, 128>>>(Y, 65536, 512, out + 7 * Hd, 32768, BROW);
    int cur = 0;
    for (int j = 2; j <= 8; j++) {
        G64W<<<dim3(8, 16), 256>>>(Y + (size_t)cur * 524288, 65536, 512, TP + 7*MM, 0,
                                   Y + (size_t)(1 - cur) * 524288, 65536, 512, 0,
                                   out + (size_t)(8 * j - 1) * Hd, 32768, BROW);
        cur ^= 1;
    }
    const float* Wg = Y + 524288;

    // 8. group-start scan (AT^64)
    zero_kernel<<<64, 256>>>(S, 65536);
    for (int g = 1; g < 8; g++)
        G64W<<<dim3(8, 2), 256>>>(S + (size_t)(g - 1) * 8 * 65536, 0, 512, TP + 14*MM, 0,
                                  S + (size_t)g * 8 * 65536, 0, 512, 0,
                                  Wg + (size_t)(g - 1) * 65536, 0, 512);

    // 9. within-group scan (AT^8), batched over groups
    for (int j = 1; j < 8; j++)
        G64W<<<dim3(8, 16), 256>>>(S + (size_t)(j - 1) * 65536, 524288, 512, TP + 7*MM, 0,
                                   S + (size_t)j * 65536, 524288, 512, 0,
                                   out + (size_t)(8 * j - 1) * Hd, 32768, BROW);

    // 10. corrections (HMMA, z = k): out[b,8c+k,:] += s_c @ AT^{k+1}
    hmma_gemm<true><<<dim3(4, 64, 8), 256, SMEM_HM>>>(
        S, 65536, 512, BSH + 1*MM, BSL + 1*MM, MM,
        out, 4096, BROW, 512);
}